// round 16
// baseline (speedup 1.0000x reference)
#include <cuda_runtime.h>

#define NN 100000
#define EE 1600000
#define GG 512
#define LL 3
#define DIM 128
#define BN_EPS 1e-5f
#define SCAN_B 1024
#define NBLK ((NN + SCAN_B - 1) / SCAN_B)   // 98
#define SB_ROW 388                          // sB k-row stride (mod 32 = 4)
#define SB_NG  48                           // sB n-group stride (mod 32 = 16)

// ---------------- scratch (static device globals; no allocation) ----------------
__device__ float4 g_A4[(size_t)NN * 32];       // activation (pre-BN after gather)
__device__ float4 g_B4[(size_t)NN * 32];       // per-layer linear output (hl)
__device__ float  g_xs[(size_t)NN * LL * DIM]; // fallback staging
__device__ float  g_deg[NN];
__device__ float  g_dinv[NN];
__device__ int    g_indeg[NN];
__device__ int    g_start[NN + 1];
__device__ int    g_cursor[NN];
__device__ int2   g_csr[EE];                   // (src, weight bits)
__device__ int    g_part[NBLK];
__device__ float  g_sumL[LL * DIM];            // per-layer BN stats
__device__ float  g_sumsqL[LL * DIM];
__device__ float  g_pool[(size_t)GG * LL * DIM]; // pre-BN per-graph segment sums
__device__ int    g_cnt[GG];

// ---------------- prep ----------------
__global__ void k_init() {
    int i = blockIdx.x * blockDim.x + threadIdx.x;
    if (i < NN) { g_deg[i] = 1.0f; g_indeg[i] = 0; }
    if (i < LL * DIM) { g_sumL[i] = 0.0f; g_sumsqL[i] = 0.0f; }
    if (i < GG) g_cnt[i] = 0;
    for (int j = i; j < GG * LL * DIM; j += gridDim.x * blockDim.x)
        g_pool[j] = 0.0f;
}

__global__ void k_deg(const int* __restrict__ ei, const float* __restrict__ ew) {
    int e = blockIdx.x * blockDim.x + threadIdx.x;
    if (e >= EE) return;
    int c = ei[EE + e];
    atomicAdd(&g_deg[c], ew[e]);
    atomicAdd(&g_indeg[c], 1);
}

__global__ void k_scan_blk() {
    __shared__ int sh[SCAN_B];
    int t = threadIdx.x;
    int i = blockIdx.x * SCAN_B + t;
    int v = (i < NN) ? g_indeg[i] : 0;
    sh[t] = v;
    __syncthreads();
    for (int off = 1; off < SCAN_B; off <<= 1) {
        int u = (t >= off) ? sh[t - off] : 0;
        __syncthreads();
        sh[t] += u;
        __syncthreads();
    }
    if (i < NN) g_start[i] = sh[t] - v;
    if (t == SCAN_B - 1) g_part[blockIdx.x] = sh[t];
}

// warp-parallel scan of the 98 block partials
__global__ void k_scan_mid() {
    int t = threadIdx.x;   // 32 threads
    int v[4];
    int s = 0;
#pragma unroll
    for (int i = 0; i < 4; ++i) {
        int idx = t * 4 + i;
        v[i] = (idx < NBLK) ? g_part[idx] : 0;
        s += v[i];
    }
    int incl = s;
    for (int off = 1; off < 32; off <<= 1) {
        int u = __shfl_up_sync(0xffffffffu, incl, off);
        if (t >= off) incl += u;
    }
    int base = incl - s;
#pragma unroll
    for (int i = 0; i < 4; ++i) {
        int idx = t * 4 + i;
        if (idx < NBLK) g_part[idx] = base;
        base += v[i];
    }
}

// scan finalize + dinv + cursor init + per-graph node counts (folded)
__global__ void k_scan_add(const int* __restrict__ batch) {
    int i = blockIdx.x * blockDim.x + threadIdx.x;
    if (i < NN) {
        int s = g_start[i] + g_part[i >> 10];
        g_start[i]  = s;
        g_cursor[i] = s;
        g_dinv[i]   = rsqrtf(g_deg[i]);
        atomicAdd(&g_cnt[batch[i]], 1);
    }
    if (i == 0) g_start[NN] = EE;
}

__global__ void k_fill(const int* __restrict__ ei, const float* __restrict__ ew) {
    int e = blockIdx.x * blockDim.x + threadIdx.x;
    if (e >= EE) return;
    int r = ei[e];
    int c = ei[EE + e];
    int slot = atomicAdd(&g_cursor[c], 1);
    float w = g_dinv[r] * ew[e] * g_dinv[c];
    g_csr[slot] = make_int2(r, __float_as_int(w));
}

// ---------------- tf32 tensor-core GEMM: C[i][j] = sum_k A'[i][k] * W[j][k] ----------------
// A' = BN-affine of A (stats_l >= 0) or A. If xs_dst != null and stats_l >= 0,
// the affine'd fp32 A values are also written to xs slice stats_l (free epilogue).
__device__ __forceinline__ unsigned f2tf(float f) {
    unsigned u;
    asm("cvt.rna.tf32.f32 %0, %1;" : "=r"(u) : "f"(f));
    return u;
}

__global__ void __launch_bounds__(128)
k_gemm_tc(const float* __restrict__ Ain, const float* __restrict__ W,
          const float* __restrict__ gamma, const float* __restrict__ beta,
          float* __restrict__ xs_dst, int mode, int stats_l, int n) {
    __shared__ unsigned sA[64 * 132];        // 33792 B
    __shared__ unsigned sB[2][4 * SB_ROW];   // 12416 B
    __shared__ float sSc[DIM], sSh[DIM];

    const float* A = mode ? (const float*)g_A4 : Ain;
    float*       C = mode ? (float*)g_B4 : (float*)g_A4;

    int tid  = threadIdx.x;
    int warp = tid >> 5;
    int lane = tid & 31;
    int row0 = blockIdx.x * 64;

    if (stats_l >= 0) {
        if (tid < DIM) {
            float mean = g_sumL[stats_l * DIM + tid] * (1.0f / NN);
            float var  = fmaxf(g_sumsqL[stats_l * DIM + tid] * (1.0f / NN) - mean * mean, 0.0f);
            float sc   = gamma[tid] * rsqrtf(var + BN_EPS);
            sSc[tid] = sc;
            sSh[tid] = beta[tid] - mean * sc;
        }
        __syncthreads();
    }

    for (int idx = tid; idx < 64 * 32; idx += 128) {
        int r = idx >> 5, c4 = idx & 31;
        int gr = row0 + r;
        float4 v = (gr < n) ? ((const float4*)A)[(size_t)gr * 32 + c4]
                            : make_float4(0.f, 0.f, 0.f, 0.f);
        if (stats_l >= 0) {
            float4 sc = *(const float4*)&sSc[c4 * 4];
            float4 sh = *(const float4*)&sSh[c4 * 4];
            v.x = fmaf(v.x, sc.x, sh.x);
            v.y = fmaf(v.y, sc.y, sh.y);
            v.z = fmaf(v.z, sc.z, sh.z);
            v.w = fmaf(v.w, sc.w, sh.w);
            if (xs_dst && gr < n)
                *(float4*)&xs_dst[(size_t)gr * (LL * DIM) + (size_t)stats_l * DIM + c4 * 4] = v;
        }
        uint4 p = make_uint4(f2tf(v.x), f2tf(v.y), f2tf(v.z), f2tf(v.w));
        *(uint4*)&sA[(size_t)r * 132 + c4 * 4] = p;
    }

    {
        const float4* wr = (const float4*)(W + (size_t)tid * 128);
        float4 w0 = wr[0], w1 = wr[1];
        unsigned base = (tid & 7) * SB_NG + (tid >> 3) * 2;
        unsigned* nb = sB[0];
        uint2 p;
        p.x = f2tf(w0.x); p.y = f2tf(w1.x); *(uint2*)&nb[base + 0 * SB_ROW] = p;
        p.x = f2tf(w0.y); p.y = f2tf(w1.y); *(uint2*)&nb[base + 1 * SB_ROW] = p;
        p.x = f2tf(w0.z); p.y = f2tf(w1.z); *(uint2*)&nb[base + 2 * SB_ROW] = p;
        p.x = f2tf(w0.w); p.y = f2tf(w1.w); *(uint2*)&nb[base + 3 * SB_ROW] = p;
    }
    __syncthreads();

    float d[16][4];
#pragma unroll
    for (int nt = 0; nt < 16; ++nt)
#pragma unroll
        for (int i = 0; i < 4; ++i) d[nt][i] = 0.0f;

    int rbase = warp * 16;
    int ar = rbase + (lane >> 2);
    int bbase = (lane & 3) * SB_ROW + (lane >> 2) * SB_NG;

    for (int ks = 0; ks < 16; ++ks) {
        int k0 = ks * 8;
        int cur = ks & 1;

        float4 w0, w1;
        if (ks < 15) {
            const float4* wr = (const float4*)(W + (size_t)tid * 128 + k0 + 8);
            w0 = wr[0]; w1 = wr[1];
        }

        unsigned a0 = sA[ar * 132 + k0 + (lane & 3)];
        unsigned a1 = sA[(ar + 8) * 132 + k0 + (lane & 3)];
        unsigned a2 = sA[ar * 132 + k0 + (lane & 3) + 4];
        unsigned a3 = sA[(ar + 8) * 132 + k0 + (lane & 3) + 4];

        const unsigned* bb = sB[cur];
#pragma unroll
        for (int ntp = 0; ntp < 8; ++ntp) {
            uint4 bv = *(const uint4*)&bb[bbase + ntp * 4];
            asm("mma.sync.aligned.m16n8k8.row.col.f32.tf32.tf32.f32 "
                "{%0,%1,%2,%3}, {%4,%5,%6,%7}, {%8,%9}, {%0,%1,%2,%3};"
                : "+f"(d[2 * ntp][0]), "+f"(d[2 * ntp][1]), "+f"(d[2 * ntp][2]), "+f"(d[2 * ntp][3])
                : "r"(a0), "r"(a1), "r"(a2), "r"(a3), "r"(bv.x), "r"(bv.y));
            asm("mma.sync.aligned.m16n8k8.row.col.f32.tf32.tf32.f32 "
                "{%0,%1,%2,%3}, {%4,%5,%6,%7}, {%8,%9}, {%0,%1,%2,%3};"
                : "+f"(d[2 * ntp + 1][0]), "+f"(d[2 * ntp + 1][1]), "+f"(d[2 * ntp + 1][2]), "+f"(d[2 * ntp + 1][3])
                : "r"(a0), "r"(a1), "r"(a2), "r"(a3), "r"(bv.z), "r"(bv.w));
        }

        if (ks < 15) {
            unsigned base = (tid & 7) * SB_NG + (tid >> 3) * 2;
            unsigned* nb = sB[cur ^ 1];
            uint2 p;
            p.x = f2tf(w0.x); p.y = f2tf(w1.x); *(uint2*)&nb[base + 0 * SB_ROW] = p;
            p.x = f2tf(w0.y); p.y = f2tf(w1.y); *(uint2*)&nb[base + 1 * SB_ROW] = p;
            p.x = f2tf(w0.z); p.y = f2tf(w1.z); *(uint2*)&nb[base + 2 * SB_ROW] = p;
            p.x = f2tf(w0.w); p.y = f2tf(w1.w); *(uint2*)&nb[base + 3 * SB_ROW] = p;
        }
        __syncthreads();
    }

    int r0 = row0 + rbase + (lane >> 2);
#pragma unroll
    for (int nt = 0; nt < 16; ++nt) {
        int col = nt * 8 + 2 * (lane & 3);
        if (r0 < n)
            *(float2*)&C[(size_t)r0 * 128 + col] = make_float2(d[nt][0], d[nt][1]);
        if (r0 + 8 < n)
            *(float2*)&C[(size_t)(r0 + 8) * 128 + col] = make_float2(d[nt][2], d[nt][3]);
    }
}

// ---------------- gather + bias + relu + fused BN stats + fused pre-BN pooling ----------------
// 512 threads = 16 warps = 16 consecutive nodes. batch sorted -> block graphs
// span [gFirst, gLast]; 16 shared pool slots; direct-atomic fallback if span > 16.
__global__ void __launch_bounds__(512)
k_gather(const float* __restrict__ bias, const int* __restrict__ batch, int l) {
    __shared__ float ssum[DIM], ssq[DIM];
    __shared__ float spool[16 * DIM];   // 8 KB
    int tid = threadIdx.x;
    if (tid < DIM) { ssum[tid] = 0.0f; ssq[tid] = 0.0f; }
#pragma unroll
    for (int i = tid; i < 16 * DIM; i += 512) spool[i] = 0.0f;
    __syncthreads();

    int node = blockIdx.x * 16 + (tid >> 5);
    int lane = tid & 31;
    int gFirst = batch[blockIdx.x * 16];

    if (node < NN) {
        float dv = g_dinv[node];
        float sw = dv * dv;
        float4 v = g_B4[(size_t)node * 32 + lane];
        float4 acc = make_float4(v.x * sw, v.y * sw, v.z * sw, v.w * sw);

        int s = g_start[node], e = g_start[node + 1];
        int j = s;
        for (; j + 3 < e; j += 4) {
            int2 c0 = g_csr[j];
            int2 c1 = g_csr[j + 1];
            int2 c2 = g_csr[j + 2];
            int2 c3 = g_csr[j + 3];
            float4 u0 = g_B4[(size_t)c0.x * 32 + lane];
            float4 u1 = g_B4[(size_t)c1.x * 32 + lane];
            float4 u2 = g_B4[(size_t)c2.x * 32 + lane];
            float4 u3 = g_B4[(size_t)c3.x * 32 + lane];
            float w0 = __int_as_float(c0.y);
            float w1 = __int_as_float(c1.y);
            float w2 = __int_as_float(c2.y);
            float w3 = __int_as_float(c3.y);
            acc.x = fmaf(w0, u0.x, acc.x); acc.y = fmaf(w0, u0.y, acc.y);
            acc.z = fmaf(w0, u0.z, acc.z); acc.w = fmaf(w0, u0.w, acc.w);
            acc.x = fmaf(w1, u1.x, acc.x); acc.y = fmaf(w1, u1.y, acc.y);
            acc.z = fmaf(w1, u1.z, acc.z); acc.w = fmaf(w1, u1.w, acc.w);
            acc.x = fmaf(w2, u2.x, acc.x); acc.y = fmaf(w2, u2.y, acc.y);
            acc.z = fmaf(w2, u2.z, acc.z); acc.w = fmaf(w2, u2.w, acc.w);
            acc.x = fmaf(w3, u3.x, acc.x); acc.y = fmaf(w3, u3.y, acc.y);
            acc.z = fmaf(w3, u3.z, acc.z); acc.w = fmaf(w3, u3.w, acc.w);
        }
        for (; j < e; ++j) {
            int2 c0 = g_csr[j];
            float4 u0 = g_B4[(size_t)c0.x * 32 + lane];
            float w0 = __int_as_float(c0.y);
            acc.x = fmaf(w0, u0.x, acc.x); acc.y = fmaf(w0, u0.y, acc.y);
            acc.z = fmaf(w0, u0.z, acc.z); acc.w = fmaf(w0, u0.w, acc.w);
        }

        float4 bc = ((const float4*)bias)[lane];
        acc.x = fmaxf(acc.x + bc.x, 0.0f);
        acc.y = fmaxf(acc.y + bc.y, 0.0f);
        acc.z = fmaxf(acc.z + bc.z, 0.0f);
        acc.w = fmaxf(acc.w + bc.w, 0.0f);
        g_A4[(size_t)node * 32 + lane] = acc;

        int cb = lane * 4;
        atomicAdd(&ssum[cb + 0], acc.x); atomicAdd(&ssq[cb + 0], acc.x * acc.x);
        atomicAdd(&ssum[cb + 1], acc.y); atomicAdd(&ssq[cb + 1], acc.y * acc.y);
        atomicAdd(&ssum[cb + 2], acc.z); atomicAdd(&ssq[cb + 2], acc.z * acc.z);
        atomicAdd(&ssum[cb + 3], acc.w); atomicAdd(&ssq[cb + 3], acc.w * acc.w);

        // pre-BN segment pooling
        int slot = batch[node] - gFirst;
        if (slot < 16) {
            atomicAdd(&spool[slot * DIM + cb + 0], acc.x);
            atomicAdd(&spool[slot * DIM + cb + 1], acc.y);
            atomicAdd(&spool[slot * DIM + cb + 2], acc.z);
            atomicAdd(&spool[slot * DIM + cb + 3], acc.w);
        } else {  // pathological span (empty graphs): direct global atomics
            size_t pb = (size_t)batch[node] * (LL * DIM) + (size_t)l * DIM + cb;
            atomicAdd(&g_pool[pb + 0], acc.x);
            atomicAdd(&g_pool[pb + 1], acc.y);
            atomicAdd(&g_pool[pb + 2], acc.z);
            atomicAdd(&g_pool[pb + 3], acc.w);
        }
    }
    __syncthreads();
    if (tid < DIM) {
        atomicAdd(&g_sumL[l * DIM + tid], ssum[tid]);
        atomicAdd(&g_sumsqL[l * DIM + tid], ssq[tid]);
        int nLast = min(blockIdx.x * 16 + 15, NN - 1);
        int smax = min(15, batch[nLast] - gFirst);
        for (int s = 0; s <= smax; ++s)
            atomicAdd(&g_pool[(size_t)(gFirst + s) * (LL * DIM) + (size_t)l * DIM + tid],
                      spool[s * DIM + tid]);
    }
}

// ---------------- final-layer xs apply (slice LL-1 only; no pooling) ----------------
__global__ void k_apply_last(float* __restrict__ xs_dst,
                             const float* __restrict__ gamma, const float* __restrict__ beta) {
    long long t = (long long)blockIdx.x * blockDim.x + threadIdx.x;
    if (t >= (long long)NN * DIM) return;
    int c = (int)(t & 127);
    long long i = t >> 7;
    const int l = LL - 1;
    float mean = g_sumL[l * DIM + c] * (1.0f / NN);
    float var  = fmaxf(g_sumsqL[l * DIM + c] * (1.0f / NN) - mean * mean, 0.0f);
    float sc   = gamma[l * DIM + c] * rsqrtf(var + BN_EPS);
    float sh   = beta[l * DIM + c] - mean * sc;
    const float* Af = (const float*)g_A4;
    xs_dst[i * (LL * DIM) + (size_t)l * DIM + c] = fmaf(Af[t], sc, sh);
}

// ---------------- pool finalize: out = sc * pre_pool + cnt * sh ----------------
__global__ void k_poolfin(float* __restrict__ out,
                          const float* __restrict__ gamma, const float* __restrict__ beta) {
    int g = blockIdx.x;      // 512
    int t = threadIdx.x;     // 384: l = t>>7, c = t&127
    int l = t >> 7, c = t & 127;
    float mean = g_sumL[l * DIM + c] * (1.0f / NN);
    float var  = fmaxf(g_sumsqL[l * DIM + c] * (1.0f / NN) - mean * mean, 0.0f);
    float sc   = gamma[l * DIM + c] * rsqrtf(var + BN_EPS);
    float sh   = beta[l * DIM + c] - mean * sc;
    out[(size_t)g * (LL * DIM) + t] =
        fmaf(sc, g_pool[(size_t)g * (LL * DIM) + t], (float)g_cnt[g] * sh);
}

__global__ void k_copy_xs(float* __restrict__ dst, long long count) {
    long long t = (long long)blockIdx.x * blockDim.x + threadIdx.x;
    if (t < count) dst[t] = g_xs[t];
}

// ---------------- launch (kernel launches ONLY) ----------------
extern "C" void kernel_launch(void* const* d_in, const int* in_sizes, int n_in,
                              void* d_out, int out_size) {
    const float* x     = (const float*)d_in[0];
    const int*   ei    = (const int*)d_in[1];
    const float* ew    = (const float*)d_in[2];
    const int*   batch = (const int*)d_in[3];
    const float* fc_w  = (const float*)d_in[4];
    const float* W     = (const float*)d_in[5];
    const float* b     = (const float*)d_in[6];
    const float* gamma = (const float*)d_in[7];
    const float* beta  = (const float*)d_in[8];

    float* out = (float*)d_out;

    const long long pool_elems = (long long)GG * LL * DIM;
    const long long xs_elems   = (long long)NN * LL * DIM;
    long long rem = (long long)out_size - pool_elems;
    bool pool_ok = ((long long)out_size >= pool_elems);
    bool direct  = (rem >= xs_elems);
    float* xs = direct ? (out + pool_elems) : g_xs;

    const int T = 256;
    int nb_N  = (NN + T - 1) / T;
    int nb_E  = (EE + T - 1) / T;
    int nb_G  = (NN + 63) / 64;
    int nb_GA = (NN + 15) / 16;
    int nb_AL = (int)(((long long)NN * DIM + T - 1) / T);

    // prep
    k_init<<<nb_N, T>>>();
    k_deg<<<nb_E, T>>>(ei, ew);
    k_scan_blk<<<NBLK, SCAN_B>>>();
    k_scan_mid<<<1, 32>>>();
    k_scan_add<<<nb_N, T>>>(batch);
    k_fill<<<nb_E, T>>>(ei, ew);

    // h0 = x @ fc_w^T -> g_A
    k_gemm_tc<<<nb_G, 128>>>(x, fc_w, gamma, beta, nullptr, 0, -1, NN);

    for (int l = 0; l < LL; ++l) {
        // hl = A' @ W[l]^T -> g_B; for l>=1 also writes xs slice l-1 (affine'd A)
        k_gemm_tc<<<nb_G, 128>>>(nullptr, W + (size_t)l * DIM * DIM,
                                 gamma + (size_t)(l > 0 ? l - 1 : 0) * DIM,
                                 beta + (size_t)(l > 0 ? l - 1 : 0) * DIM,
                                 l > 0 ? xs : nullptr, 1, l - 1, NN);
        k_gather<<<nb_GA, 512>>>(b + (size_t)l * DIM, batch, l);
    }

    // last layer's xs slice + pooled output
    k_apply_last<<<nb_AL, T>>>(xs, gamma, beta);
    if (pool_ok)
        k_poolfin<<<GG, LL * DIM>>>(out, gamma, beta);

    if (!direct && rem > 0) {
        long long cnt = rem < xs_elems ? rem : xs_elems;
        int nb_CP = (int)((cnt + T - 1) / T);
        k_copy_xs<<<nb_CP, T>>>(out + pool_elems, cnt);
    }
}